// round 9
// baseline (speedup 1.0000x reference)
#include <cuda_runtime.h>
#include <math.h>

// ---------------------------------------------------------------------------
// ONE persistent kernel = ONE graph node (fixes the 4MB graph-upload residue).
// 128 CTAs x 128 threads, all co-resident (<=148 SMs) -> software grid barrier.
//
// Pipeline per RK4 f-eval:
//   G1   : partials of A @ W1      (64 N-tiles x split-K2 = 128 jobs)
//   redH : H = tanh(P1a+P1b+b1)    (elementwise)
//   G2   : partials of H @ W2      (50 N-tiles x split-K2 = 100 jobs)
//   upd  : k = P2a+P2b+b2 ; RK4 state update (+ trajectory store on k4)
// 4 grid barriers per f-eval.
//
// GEMM tile: C(128x64), 128 threads, per-thread 8x8 via packed fma.rn.f32x2
// with diag/anti-diag pairing: A[k][m] and B[k][n] smem both give natural
// f32x2 pairs (4 LDS.128/kk, heavy broadcast -> ~6 crossbar cyc vs 64 fma cyc).
// Cross-CTA global reads use __ldcg (L1 not coherent within one launch).
// ---------------------------------------------------------------------------

#define BATCH   128
#define STATE   3200
#define OHID    4096
#define NSTEPS  192
#define NCTA    128
#define NTHR    128

constexpr float DT  = (float)(8.0 / 191.0);   // matches jnp f64->f32
constexpr float HDT = 0.5f * DT;
constexpr float DT6 = DT / 6.0f;

// -------------------- device scratch (no allocation allowed) ----------------
__device__ __align__(16) float g_embs[BATCH * 2048];
__device__ __align__(16) float g_Y   [BATCH * STATE];
__device__ __align__(16) float g_TMP [BATCH * STATE];
__device__ __align__(16) float g_ACC [BATCH * STATE];
__device__ __align__(16) float g_H   [BATCH * OHID];
__device__ __align__(16) float g_P1  [2 * BATCH * OHID];   // GEMM1 split-K partials
__device__ __align__(16) float g_P2  [2 * BATCH * STATE];  // GEMM2 split-K partials
__device__ unsigned          g_cnt;     // grid barrier arrival counter
__device__ volatile unsigned g_gen;     // grid barrier generation

// ------------------------------- primitives ---------------------------------
__device__ __forceinline__ unsigned long long pk(float lo, float hi) {
    unsigned long long r;
    asm("mov.b64 %0, {%1, %2};" : "=l"(r) : "f"(lo), "f"(hi));
    return r;
}
__device__ __forceinline__ float2 upk(unsigned long long v) {
    float2 f;
    asm("mov.b64 {%0, %1}, %2;" : "=f"(f.x), "=f"(f.y) : "l"(v));
    return f;
}
__device__ __forceinline__ void ffma2(unsigned long long& d,
                                      unsigned long long a, unsigned long long b) {
    asm("fma.rn.f32x2 %0, %1, %2, %0;" : "+l"(d) : "l"(a), "l"(b));
}
__device__ __forceinline__ float4 ldcg4(const float* p) {
    return __ldcg(reinterpret_cast<const float4*>(p));
}

// Software grid barrier: sense-reversing generation counter. Safe because all
// 128 CTAs are co-resident (grid <= SM count, 1 CTA/SM).
__device__ __forceinline__ void gridbar() {
    __syncthreads();
    if (threadIdx.x == 0) {
        const unsigned my = g_gen;          // read BEFORE arrival
        __threadfence();
        if (atomicAdd(&g_cnt, 1u) == NCTA - 1u) {
            g_cnt = 0u;
            __threadfence();
            g_gen = my + 1u;                // release
        } else {
            while (g_gen == my) { }         // spin (volatile)
        }
        __threadfence();
    }
    __syncthreads();
}

// ------------------------------ GEMM tile job --------------------------------
// Partial C(128 x 64) = A(128 x lda)[:, kbeg : kbeg+16*nblk] @ W[ , n0:n0+64]
// stored raw to P (row stride ldp). 128 threads, per-thread 8x8.
__device__ void gemm_job(const float* __restrict__ A, int lda,
                         const float* __restrict__ W, int ldw,
                         int kbeg, int nblk, int n0,
                         float* __restrict__ P, int ldp) {
    __shared__ __align__(16) float As[16][128];   // [k][m]
    __shared__ __align__(16) float Bs[16][64];    // [k][n]

    const int tid = threadIdx.x;
    const int tm  = (tid >> 3) * 8;      // m base (0..120)
    const int tn  = (tid & 7) * 8;       // n base (0..56)
    const int br  = tid >> 3;            // W row within 16-k block (0..15)
    const int bc  = (tid & 7) * 8;       // W col offset within 64

    const float* Ar = A + (size_t)tid * lda + kbeg;          // A row m = tid
    const float* Wr = W + (size_t)(kbeg + br) * ldw + n0 + bc;
    const size_t wstep = (size_t)16 * ldw;

    unsigned long long accd[4][4], accx[4][4];
#pragma unroll
    for (int i = 0; i < 4; i++)
#pragma unroll
        for (int j = 0; j < 4; j++) { accd[i][j] = 0ull; accx[i][j] = 0ull; }

    float4 a0, a1, a2, a3, b0, b1;

#define LDG_BLK(bk)                                            \
    do {                                                       \
        const float* Ab = Ar + (bk) * 16;                      \
        a0 = ldcg4(Ab + 0);  a1 = ldcg4(Ab + 4);               \
        a2 = ldcg4(Ab + 8);  a3 = ldcg4(Ab + 12);              \
        const float* Wb = Wr + (size_t)(bk) * wstep;           \
        b0 = *(const float4*)(Wb + 0);                         \
        b1 = *(const float4*)(Wb + 4);                         \
    } while (0)

    LDG_BLK(0);

    for (int bk = 0; bk < nblk; bk++) {
        // stage current prefetch into smem
        As[ 0][tid] = a0.x; As[ 1][tid] = a0.y; As[ 2][tid] = a0.z; As[ 3][tid] = a0.w;
        As[ 4][tid] = a1.x; As[ 5][tid] = a1.y; As[ 6][tid] = a1.z; As[ 7][tid] = a1.w;
        As[ 8][tid] = a2.x; As[ 9][tid] = a2.y; As[10][tid] = a2.z; As[11][tid] = a2.w;
        As[12][tid] = a3.x; As[13][tid] = a3.y; As[14][tid] = a3.z; As[15][tid] = a3.w;
        *(float4*)&Bs[br][bc]     = b0;
        *(float4*)&Bs[br][bc + 4] = b1;
        __syncthreads();

        if (bk + 1 < nblk) LDG_BLK(bk + 1);

#pragma unroll
        for (int kk = 0; kk < 16; kk++) {
            const float4 av0 = *(const float4*)&As[kk][tm];
            const float4 av1 = *(const float4*)&As[kk][tm + 4];
            const float4 bv0 = *(const float4*)&Bs[kk][tn];
            const float4 bv1 = *(const float4*)&Bs[kk][tn + 4];
            const unsigned long long ap[4] = {
                pk(av0.x, av0.y), pk(av0.z, av0.w),
                pk(av1.x, av1.y), pk(av1.z, av1.w) };
            const unsigned long long bp[4] = {
                pk(bv0.x, bv0.y), pk(bv0.z, bv0.w),
                pk(bv1.x, bv1.y), pk(bv1.z, bv1.w) };
            const unsigned long long bw[4] = {
                pk(bv0.y, bv0.x), pk(bv0.w, bv0.z),
                pk(bv1.y, bv1.x), pk(bv1.w, bv1.z) };
#pragma unroll
            for (int i = 0; i < 4; i++)
#pragma unroll
                for (int j = 0; j < 4; j++) {
                    ffma2(accd[i][j], ap[i], bp[j]);   // (r0,c0),(r1,c1)
                    ffma2(accx[i][j], ap[i], bw[j]);   // (r0,c1),(r1,c0)
                }
        }
        __syncthreads();
    }
#undef LDG_BLK

    // write raw partials
#pragma unroll
    for (int i = 0; i < 4; i++) {
        const int r0 = tm + 2 * i;
#pragma unroll
        for (int j = 0; j < 4; j++) {
            const int c0 = n0 + tn + 2 * j;
            const float2 d = upk(accd[i][j]);   // d.x=C[r0][c0], d.y=C[r1][c1]
            const float2 x = upk(accx[i][j]);   // x.x=C[r0][c1], x.y=C[r1][c0]
            *(float2*)&P[(size_t)r0 * ldp + c0]       = make_float2(d.x, x.x);
            *(float2*)&P[(size_t)(r0 + 1) * ldp + c0] = make_float2(x.y, d.y);
        }
    }
}

// ------------------------------ persistent kernel ----------------------------
__global__ void __launch_bounds__(NTHR, 1)
persist_kernel(const float* __restrict__ z,
               const float* __restrict__ decW, const float* __restrict__ decb,
               const float* __restrict__ templ,
               const float* __restrict__ dW1, const float* __restrict__ db1,
               const float* __restrict__ dW2, const float* __restrict__ db2,
               const float* __restrict__ aW1, const float* __restrict__ ab1,
               const float* __restrict__ aW2, const float* __restrict__ ab2,
               const float* __restrict__ W1, const float* __restrict__ b1,
               const float* __restrict__ W2, const float* __restrict__ b2,
               float* __restrict__ out) {
    const int cta = blockIdx.x;
    const int tid = threadIdx.x;

    // ---------------- P0: decoder GEMM (B=128 rows, one per CTA) ------------
    {
        __shared__ float zs[128];
        zs[tid] = z[cta * 128 + tid];
        __syncthreads();
        for (int c = tid; c < 2048; c += NTHR) {
            float acc = decb[c];
#pragma unroll 8
            for (int k = 0; k < 128; k++) acc += zs[k] * decW[k * 2048 + c];
            g_embs[cta * 2048 + c] = acc;
        }
        __syncthreads();
    }
    gridbar();

    // ---------------- P1: per-(batch,slot) init -> y0 + out[0] --------------
    {
        __shared__ float e[64];
        __shared__ float h[128];
        __shared__ float ah[32];
        __shared__ float alive_s;
        for (int job = cta; job < BATCH * 32; job += NCTA) {   // exactly 32 iters
            const int b = job >> 5;
            const int s = job & 31;
            if (tid < 64) e[tid] = __ldcg(&g_embs[b * 2048 + s * 64 + tid]);
            __syncthreads();
            {
                float acc = db1[tid];
#pragma unroll 8
                for (int i = 0; i < 64; i++) acc += e[i] * dW1[i * 128 + tid];
                h[tid] = fmaxf(acc, 0.f);
            }
            if (tid < 32) {
                float acc = ab1[tid];
#pragma unroll 8
                for (int i = 0; i < 64; i++) acc += e[i] * aW1[i * 32 + tid];
                ah[tid] = fmaxf(acc, 0.f);
            }
            __syncthreads();
            if (tid == 0) {
                float l = ab2[0];
#pragma unroll
                for (int j = 0; j < 32; j++) l += ah[j] * aW2[j];
                alive_s = 1.f / (1.f + expf(-l));
            }
            __syncthreads();
            const float alive = alive_s;
            if (tid < 99) {
                float acc = db2[tid] + templ[s * 99 + tid];
#pragma unroll 8
                for (int j = 0; j < 128; j++) acc += h[j] * dW2[j * 99 + tid];
                const float v = acc * alive;
                const int idx = b * STATE + s * 99 + tid;
                g_Y[idx] = v;
                out[idx] = v;
            }
            if (tid == 99) {
                const int idx = b * STATE + 3168 + s;
                g_Y[idx] = alive;
                out[idx] = alive;
            }
            __syncthreads();   // before next job reuses e/h
        }
    }
    gridbar();

    // ---------------- main RK4 loop -----------------------------------------
    for (int s = 1; s < NSTEPS; s++) {
        float* so = out + (size_t)s * BATCH * STATE;

        for (int ev = 0; ev < 4; ev++) {
            const float* Ain = (ev == 0) ? g_Y : g_TMP;

            // ---- G1: partials of A @ W1 (128 jobs = 64 tiles x 2 k-halves)
            {
                const int tile = cta & 63;
                const int kh   = cta >> 6;
                gemm_job(Ain, STATE, W1, OHID, kh * 1600, 100, tile * 64,
                         g_P1 + (size_t)kh * BATCH * OHID, OHID);
            }
            gridbar();

            // ---- reduce: H = tanh(P1a + P1b + b1)   (row cta of 128x4096)
            {
                const float* Pa = g_P1;
                const float* Pb = g_P1 + BATCH * OHID;
                const int base  = cta * OHID;
#pragma unroll
                for (int c = tid * 4; c < OHID; c += NTHR * 4) {
                    const float4 pa = ldcg4(Pa + base + c);
                    const float4 pb = ldcg4(Pb + base + c);
                    const float4 bb = *(const float4*)(b1 + c);
                    float4 hv;
                    hv.x = tanhf(pa.x + pb.x + bb.x);
                    hv.y = tanhf(pa.y + pb.y + bb.y);
                    hv.z = tanhf(pa.z + pb.z + bb.z);
                    hv.w = tanhf(pa.w + pb.w + bb.w);
                    *(float4*)&g_H[base + c] = hv;
                }
            }
            gridbar();

            // ---- G2: partials of H @ W2 (100 jobs = 50 tiles x 2 k-halves)
            if (cta < 100) {
                const int tile = cta % 50;
                const int kh   = cta / 50;
                gemm_job(g_H, OHID, W2, STATE, kh * 2048, 128, tile * 64,
                         g_P2 + (size_t)kh * BATCH * STATE, STATE);
            }
            gridbar();

            // ---- update: k = P2a + P2b + b2 ; RK4 state math (row cta)
            {
                const float* Pa = g_P2;
                const float* Pb = g_P2 + BATCH * STATE;
                const int base  = cta * STATE;
                for (int c = tid * 4; c < STATE; c += NTHR * 4) {
                    const int i = base + c;
                    const float4 pa = ldcg4(Pa + i);
                    const float4 pb = ldcg4(Pb + i);
                    const float4 bb = *(const float4*)(b2 + c);
                    float4 k;
                    k.x = pa.x + pb.x + bb.x;
                    k.y = pa.y + pb.y + bb.y;
                    k.z = pa.z + pb.z + bb.z;
                    k.w = pa.w + pb.w + bb.w;
                    const float4 y = __ldcg((const float4*)(g_Y + i));
                    if (ev == 0) {
                        *(float4*)&g_ACC[i] = k;
                        float4 t;
                        t.x = y.x + HDT * k.x; t.y = y.y + HDT * k.y;
                        t.z = y.z + HDT * k.z; t.w = y.w + HDT * k.w;
                        *(float4*)&g_TMP[i] = t;
                    } else if (ev == 1) {
                        float4 a = *(const float4*)&g_ACC[i];
                        a.x += 2.f * k.x; a.y += 2.f * k.y;
                        a.z += 2.f * k.z; a.w += 2.f * k.w;
                        *(float4*)&g_ACC[i] = a;
                        float4 t;
                        t.x = y.x + HDT * k.x; t.y = y.y + HDT * k.y;
                        t.z = y.z + HDT * k.z; t.w = y.w + HDT * k.w;
                        *(float4*)&g_TMP[i] = t;
                    } else if (ev == 2) {
                        float4 a = *(const float4*)&g_ACC[i];
                        a.x += 2.f * k.x; a.y += 2.f * k.y;
                        a.z += 2.f * k.z; a.w += 2.f * k.w;
                        *(float4*)&g_ACC[i] = a;
                        float4 t;
                        t.x = y.x + DT * k.x; t.y = y.y + DT * k.y;
                        t.z = y.z + DT * k.z; t.w = y.w + DT * k.w;
                        *(float4*)&g_TMP[i] = t;
                    } else {
                        const float4 a = *(const float4*)&g_ACC[i];
                        float4 yn;
                        yn.x = y.x + DT6 * (a.x + k.x);
                        yn.y = y.y + DT6 * (a.y + k.y);
                        yn.z = y.z + DT6 * (a.z + k.z);
                        yn.w = y.w + DT6 * (a.w + k.w);
                        *(float4*)&g_Y[i] = yn;
                        *(float4*)&so[i]  = yn;
                    }
                }
            }
            gridbar();
        }
    }
}

// ------------------------------ launcher ------------------------------------
extern "C" void kernel_launch(void* const* d_in, const int* in_sizes, int n_in,
                              void* d_out, int out_size) {
    (void)in_sizes; (void)n_in; (void)out_size;

    const float* z      = (const float*)d_in[0];
    const float* dec_W  = (const float*)d_in[1];
    const float* dec_b  = (const float*)d_in[2];
    const float* templ  = (const float*)d_in[3];
    const float* def_W1 = (const float*)d_in[4];
    const float* def_b1 = (const float*)d_in[5];
    const float* def_W2 = (const float*)d_in[6];
    const float* def_b2 = (const float*)d_in[7];
    const float* al_W1  = (const float*)d_in[8];
    const float* al_b1  = (const float*)d_in[9];
    const float* al_W2  = (const float*)d_in[10];
    const float* al_b2  = (const float*)d_in[11];
    const float* ode_W1 = (const float*)d_in[12];
    const float* ode_b1 = (const float*)d_in[13];
    const float* ode_W2 = (const float*)d_in[14];
    const float* ode_b2 = (const float*)d_in[15];
    float* out = (float*)d_out;

    persist_kernel<<<NCTA, NTHR>>>(z, dec_W, dec_b, templ,
                                   def_W1, def_b1, def_W2, def_b2,
                                   al_W1, al_b1, al_W2, al_b2,
                                   ode_W1, ode_b1, ode_W2, ode_b2, out);
}

// round 10
// speedup vs baseline: 1.0004x; 1.0004x over previous
#include <cuda_runtime.h>
#include <math.h>

// ---------------------------------------------------------------------------
// ONE persistent kernel = ONE graph node (fixes the 4MB graph-upload residue).
// 128 CTAs x 128 threads, all co-resident (<=148 SMs) -> software grid barrier.
//
// Pipeline per RK4 f-eval:
//   G1   : partials of A @ W1      (64 N-tiles x split-K2 = 128 jobs)
//   redH : H = tanh(P1a+P1b+b1)    (elementwise)
//   G2   : partials of H @ W2      (50 N-tiles x split-K2 = 100 jobs)
//   upd  : k = P2a+P2b+b2 ; RK4 state update (+ trajectory store on k4)
// 4 grid barriers per f-eval.
//
// GEMM tile: C(128x64), 128 threads, per-thread 8x8 via packed fma.rn.f32x2
// with diag/anti-diag pairing: A[k][m] and B[k][n] smem both give natural
// f32x2 pairs (4 LDS.128/kk, heavy broadcast -> ~6 crossbar cyc vs 64 fma cyc).
// Cross-CTA global reads use __ldcg (L1 not coherent within one launch).
// ---------------------------------------------------------------------------

#define BATCH   128
#define STATE   3200
#define OHID    4096
#define NSTEPS  192
#define NCTA    128
#define NTHR    128

constexpr float DT  = (float)(8.0 / 191.0);   // matches jnp f64->f32
constexpr float HDT = 0.5f * DT;
constexpr float DT6 = DT / 6.0f;

// -------------------- device scratch (no allocation allowed) ----------------
__device__ __align__(16) float g_embs[BATCH * 2048];
__device__ __align__(16) float g_Y   [BATCH * STATE];
__device__ __align__(16) float g_TMP [BATCH * STATE];
__device__ __align__(16) float g_ACC [BATCH * STATE];
__device__ __align__(16) float g_H   [BATCH * OHID];
__device__ __align__(16) float g_P1  [2 * BATCH * OHID];   // GEMM1 split-K partials
__device__ __align__(16) float g_P2  [2 * BATCH * STATE];  // GEMM2 split-K partials
__device__ unsigned          g_cnt;     // grid barrier arrival counter
__device__ volatile unsigned g_gen;     // grid barrier generation

// ------------------------------- primitives ---------------------------------
__device__ __forceinline__ unsigned long long pk(float lo, float hi) {
    unsigned long long r;
    asm("mov.b64 %0, {%1, %2};" : "=l"(r) : "f"(lo), "f"(hi));
    return r;
}
__device__ __forceinline__ float2 upk(unsigned long long v) {
    float2 f;
    asm("mov.b64 {%0, %1}, %2;" : "=f"(f.x), "=f"(f.y) : "l"(v));
    return f;
}
__device__ __forceinline__ void ffma2(unsigned long long& d,
                                      unsigned long long a, unsigned long long b) {
    asm("fma.rn.f32x2 %0, %1, %2, %0;" : "+l"(d) : "l"(a), "l"(b));
}
__device__ __forceinline__ float4 ldcg4(const float* p) {
    return __ldcg(reinterpret_cast<const float4*>(p));
}

// Software grid barrier: sense-reversing generation counter. Safe because all
// 128 CTAs are co-resident (grid <= SM count, 1 CTA/SM).
__device__ __forceinline__ void gridbar() {
    __syncthreads();
    if (threadIdx.x == 0) {
        const unsigned my = g_gen;          // read BEFORE arrival
        __threadfence();
        if (atomicAdd(&g_cnt, 1u) == NCTA - 1u) {
            g_cnt = 0u;
            __threadfence();
            g_gen = my + 1u;                // release
        } else {
            while (g_gen == my) { }         // spin (volatile)
        }
        __threadfence();
    }
    __syncthreads();
}

// ------------------------------ GEMM tile job --------------------------------
// Partial C(128 x 64) = A(128 x lda)[:, kbeg : kbeg+16*nblk] @ W[ , n0:n0+64]
// stored raw to P (row stride ldp). 128 threads, per-thread 8x8.
__device__ void gemm_job(const float* __restrict__ A, int lda,
                         const float* __restrict__ W, int ldw,
                         int kbeg, int nblk, int n0,
                         float* __restrict__ P, int ldp) {
    __shared__ __align__(16) float As[16][128];   // [k][m]
    __shared__ __align__(16) float Bs[16][64];    // [k][n]

    const int tid = threadIdx.x;
    const int tm  = (tid >> 3) * 8;      // m base (0..120)
    const int tn  = (tid & 7) * 8;       // n base (0..56)
    const int br  = tid >> 3;            // W row within 16-k block (0..15)
    const int bc  = (tid & 7) * 8;       // W col offset within 64

    const float* Ar = A + (size_t)tid * lda + kbeg;          // A row m = tid
    const float* Wr = W + (size_t)(kbeg + br) * ldw + n0 + bc;
    const size_t wstep = (size_t)16 * ldw;

    unsigned long long accd[4][4], accx[4][4];
#pragma unroll
    for (int i = 0; i < 4; i++)
#pragma unroll
        for (int j = 0; j < 4; j++) { accd[i][j] = 0ull; accx[i][j] = 0ull; }

    float4 a0, a1, a2, a3, b0, b1;

#define LDG_BLK(bk)                                            \
    do {                                                       \
        const float* Ab = Ar + (bk) * 16;                      \
        a0 = ldcg4(Ab + 0);  a1 = ldcg4(Ab + 4);               \
        a2 = ldcg4(Ab + 8);  a3 = ldcg4(Ab + 12);              \
        const float* Wb = Wr + (size_t)(bk) * wstep;           \
        b0 = *(const float4*)(Wb + 0);                         \
        b1 = *(const float4*)(Wb + 4);                         \
    } while (0)

    LDG_BLK(0);

    for (int bk = 0; bk < nblk; bk++) {
        // stage current prefetch into smem
        As[ 0][tid] = a0.x; As[ 1][tid] = a0.y; As[ 2][tid] = a0.z; As[ 3][tid] = a0.w;
        As[ 4][tid] = a1.x; As[ 5][tid] = a1.y; As[ 6][tid] = a1.z; As[ 7][tid] = a1.w;
        As[ 8][tid] = a2.x; As[ 9][tid] = a2.y; As[10][tid] = a2.z; As[11][tid] = a2.w;
        As[12][tid] = a3.x; As[13][tid] = a3.y; As[14][tid] = a3.z; As[15][tid] = a3.w;
        *(float4*)&Bs[br][bc]     = b0;
        *(float4*)&Bs[br][bc + 4] = b1;
        __syncthreads();

        if (bk + 1 < nblk) LDG_BLK(bk + 1);

#pragma unroll
        for (int kk = 0; kk < 16; kk++) {
            const float4 av0 = *(const float4*)&As[kk][tm];
            const float4 av1 = *(const float4*)&As[kk][tm + 4];
            const float4 bv0 = *(const float4*)&Bs[kk][tn];
            const float4 bv1 = *(const float4*)&Bs[kk][tn + 4];
            const unsigned long long ap[4] = {
                pk(av0.x, av0.y), pk(av0.z, av0.w),
                pk(av1.x, av1.y), pk(av1.z, av1.w) };
            const unsigned long long bp[4] = {
                pk(bv0.x, bv0.y), pk(bv0.z, bv0.w),
                pk(bv1.x, bv1.y), pk(bv1.z, bv1.w) };
            const unsigned long long bw[4] = {
                pk(bv0.y, bv0.x), pk(bv0.w, bv0.z),
                pk(bv1.y, bv1.x), pk(bv1.w, bv1.z) };
#pragma unroll
            for (int i = 0; i < 4; i++)
#pragma unroll
                for (int j = 0; j < 4; j++) {
                    ffma2(accd[i][j], ap[i], bp[j]);   // (r0,c0),(r1,c1)
                    ffma2(accx[i][j], ap[i], bw[j]);   // (r0,c1),(r1,c0)
                }
        }
        __syncthreads();
    }
#undef LDG_BLK

    // write raw partials
#pragma unroll
    for (int i = 0; i < 4; i++) {
        const int r0 = tm + 2 * i;
#pragma unroll
        for (int j = 0; j < 4; j++) {
            const int c0 = n0 + tn + 2 * j;
            const float2 d = upk(accd[i][j]);   // d.x=C[r0][c0], d.y=C[r1][c1]
            const float2 x = upk(accx[i][j]);   // x.x=C[r0][c1], x.y=C[r1][c0]
            *(float2*)&P[(size_t)r0 * ldp + c0]       = make_float2(d.x, x.x);
            *(float2*)&P[(size_t)(r0 + 1) * ldp + c0] = make_float2(x.y, d.y);
        }
    }
}

// ------------------------------ persistent kernel ----------------------------
__global__ void __launch_bounds__(NTHR, 1)
persist_kernel(const float* __restrict__ z,
               const float* __restrict__ decW, const float* __restrict__ decb,
               const float* __restrict__ templ,
               const float* __restrict__ dW1, const float* __restrict__ db1,
               const float* __restrict__ dW2, const float* __restrict__ db2,
               const float* __restrict__ aW1, const float* __restrict__ ab1,
               const float* __restrict__ aW2, const float* __restrict__ ab2,
               const float* __restrict__ W1, const float* __restrict__ b1,
               const float* __restrict__ W2, const float* __restrict__ b2,
               float* __restrict__ out) {
    const int cta = blockIdx.x;
    const int tid = threadIdx.x;

    // ---------------- P0: decoder GEMM (B=128 rows, one per CTA) ------------
    {
        __shared__ float zs[128];
        zs[tid] = z[cta * 128 + tid];
        __syncthreads();
        for (int c = tid; c < 2048; c += NTHR) {
            float acc = decb[c];
#pragma unroll 8
            for (int k = 0; k < 128; k++) acc += zs[k] * decW[k * 2048 + c];
            g_embs[cta * 2048 + c] = acc;
        }
        __syncthreads();
    }
    gridbar();

    // ---------------- P1: per-(batch,slot) init -> y0 + out[0] --------------
    {
        __shared__ float e[64];
        __shared__ float h[128];
        __shared__ float ah[32];
        __shared__ float alive_s;
        for (int job = cta; job < BATCH * 32; job += NCTA) {   // exactly 32 iters
            const int b = job >> 5;
            const int s = job & 31;
            if (tid < 64) e[tid] = __ldcg(&g_embs[b * 2048 + s * 64 + tid]);
            __syncthreads();
            {
                float acc = db1[tid];
#pragma unroll 8
                for (int i = 0; i < 64; i++) acc += e[i] * dW1[i * 128 + tid];
                h[tid] = fmaxf(acc, 0.f);
            }
            if (tid < 32) {
                float acc = ab1[tid];
#pragma unroll 8
                for (int i = 0; i < 64; i++) acc += e[i] * aW1[i * 32 + tid];
                ah[tid] = fmaxf(acc, 0.f);
            }
            __syncthreads();
            if (tid == 0) {
                float l = ab2[0];
#pragma unroll
                for (int j = 0; j < 32; j++) l += ah[j] * aW2[j];
                alive_s = 1.f / (1.f + expf(-l));
            }
            __syncthreads();
            const float alive = alive_s;
            if (tid < 99) {
                float acc = db2[tid] + templ[s * 99 + tid];
#pragma unroll 8
                for (int j = 0; j < 128; j++) acc += h[j] * dW2[j * 99 + tid];
                const float v = acc * alive;
                const int idx = b * STATE + s * 99 + tid;
                g_Y[idx] = v;
                out[idx] = v;
            }
            if (tid == 99) {
                const int idx = b * STATE + 3168 + s;
                g_Y[idx] = alive;
                out[idx] = alive;
            }
            __syncthreads();   // before next job reuses e/h
        }
    }
    gridbar();

    // ---------------- main RK4 loop -----------------------------------------
    for (int s = 1; s < NSTEPS; s++) {
        float* so = out + (size_t)s * BATCH * STATE;

        for (int ev = 0; ev < 4; ev++) {
            const float* Ain = (ev == 0) ? g_Y : g_TMP;

            // ---- G1: partials of A @ W1 (128 jobs = 64 tiles x 2 k-halves)
            {
                const int tile = cta & 63;
                const int kh   = cta >> 6;
                gemm_job(Ain, STATE, W1, OHID, kh * 1600, 100, tile * 64,
                         g_P1 + (size_t)kh * BATCH * OHID, OHID);
            }
            gridbar();

            // ---- reduce: H = tanh(P1a + P1b + b1)   (row cta of 128x4096)
            {
                const float* Pa = g_P1;
                const float* Pb = g_P1 + BATCH * OHID;
                const int base  = cta * OHID;
#pragma unroll
                for (int c = tid * 4; c < OHID; c += NTHR * 4) {
                    const float4 pa = ldcg4(Pa + base + c);
                    const float4 pb = ldcg4(Pb + base + c);
                    const float4 bb = *(const float4*)(b1 + c);
                    float4 hv;
                    hv.x = tanhf(pa.x + pb.x + bb.x);
                    hv.y = tanhf(pa.y + pb.y + bb.y);
                    hv.z = tanhf(pa.z + pb.z + bb.z);
                    hv.w = tanhf(pa.w + pb.w + bb.w);
                    *(float4*)&g_H[base + c] = hv;
                }
            }
            gridbar();

            // ---- G2: partials of H @ W2 (100 jobs = 50 tiles x 2 k-halves)
            if (cta < 100) {
                const int tile = cta % 50;
                const int kh   = cta / 50;
                gemm_job(g_H, OHID, W2, STATE, kh * 2048, 128, tile * 64,
                         g_P2 + (size_t)kh * BATCH * STATE, STATE);
            }
            gridbar();

            // ---- update: k = P2a + P2b + b2 ; RK4 state math (row cta)
            {
                const float* Pa = g_P2;
                const float* Pb = g_P2 + BATCH * STATE;
                const int base  = cta * STATE;
                for (int c = tid * 4; c < STATE; c += NTHR * 4) {
                    const int i = base + c;
                    const float4 pa = ldcg4(Pa + i);
                    const float4 pb = ldcg4(Pb + i);
                    const float4 bb = *(const float4*)(b2 + c);
                    float4 k;
                    k.x = pa.x + pb.x + bb.x;
                    k.y = pa.y + pb.y + bb.y;
                    k.z = pa.z + pb.z + bb.z;
                    k.w = pa.w + pb.w + bb.w;
                    const float4 y = __ldcg((const float4*)(g_Y + i));
                    if (ev == 0) {
                        *(float4*)&g_ACC[i] = k;
                        float4 t;
                        t.x = y.x + HDT * k.x; t.y = y.y + HDT * k.y;
                        t.z = y.z + HDT * k.z; t.w = y.w + HDT * k.w;
                        *(float4*)&g_TMP[i] = t;
                    } else if (ev == 1) {
                        float4 a = *(const float4*)&g_ACC[i];
                        a.x += 2.f * k.x; a.y += 2.f * k.y;
                        a.z += 2.f * k.z; a.w += 2.f * k.w;
                        *(float4*)&g_ACC[i] = a;
                        float4 t;
                        t.x = y.x + HDT * k.x; t.y = y.y + HDT * k.y;
                        t.z = y.z + HDT * k.z; t.w = y.w + HDT * k.w;
                        *(float4*)&g_TMP[i] = t;
                    } else if (ev == 2) {
                        float4 a = *(const float4*)&g_ACC[i];
                        a.x += 2.f * k.x; a.y += 2.f * k.y;
                        a.z += 2.f * k.z; a.w += 2.f * k.w;
                        *(float4*)&g_ACC[i] = a;
                        float4 t;
                        t.x = y.x + DT * k.x; t.y = y.y + DT * k.y;
                        t.z = y.z + DT * k.z; t.w = y.w + DT * k.w;
                        *(float4*)&g_TMP[i] = t;
                    } else {
                        const float4 a = *(const float4*)&g_ACC[i];
                        float4 yn;
                        yn.x = y.x + DT6 * (a.x + k.x);
                        yn.y = y.y + DT6 * (a.y + k.y);
                        yn.z = y.z + DT6 * (a.z + k.z);
                        yn.w = y.w + DT6 * (a.w + k.w);
                        *(float4*)&g_Y[i] = yn;
                        *(float4*)&so[i]  = yn;
                    }
                }
            }
            gridbar();
        }
    }
}

// ------------------------------ launcher ------------------------------------
extern "C" void kernel_launch(void* const* d_in, const int* in_sizes, int n_in,
                              void* d_out, int out_size) {
    (void)in_sizes; (void)n_in; (void)out_size;

    const float* z      = (const float*)d_in[0];
    const float* dec_W  = (const float*)d_in[1];
    const float* dec_b  = (const float*)d_in[2];
    const float* templ  = (const float*)d_in[3];
    const float* def_W1 = (const float*)d_in[4];
    const float* def_b1 = (const float*)d_in[5];
    const float* def_W2 = (const float*)d_in[6];
    const float* def_b2 = (const float*)d_in[7];
    const float* al_W1  = (const float*)d_in[8];
    const float* al_b1  = (const float*)d_in[9];
    const float* al_W2  = (const float*)d_in[10];
    const float* al_b2  = (const float*)d_in[11];
    const float* ode_W1 = (const float*)d_in[12];
    const float* ode_b1 = (const float*)d_in[13];
    const float* ode_W2 = (const float*)d_in[14];
    const float* ode_b2 = (const float*)d_in[15];
    float* out = (float*)d_out;

    persist_kernel<<<NCTA, NTHR>>>(z, dec_W, dec_b, templ,
                                   def_W1, def_b1, def_W2, def_b2,
                                   al_W1, al_b1, al_W2, al_b2,
                                   ode_W1, ode_b1, ode_W2, ode_b2, out);
}